// round 1
// baseline (speedup 1.0000x reference)
#include <cuda_runtime.h>
#include <cstdint>

// Problem constants (fixed by the dataset).
#define NMAX 100000
#define EMAX 3200000

// Scratch (device globals -- no allocation allowed).
__device__ float g_deg[NMAX];
__device__ float g_dis[NMAX];
__device__ float g_h1s[NMAX * 64];   // (x@W1) * dis[row]
__device__ float g_agg1[NMAX * 64];  // sum over incoming edges of g_h1s[src]
__device__ float g_h2s[NMAX * 32];   // (h@W2) * dis[row]
__device__ float g_agg2[NMAX * 32];

// ---------------------------------------------------------------------------
// init: deg = 1 (self loop)
__global__ void k_init_deg(int n) {
    int i = blockIdx.x * blockDim.x + threadIdx.x;
    if (i < n) g_deg[i] = 1.0f;
}

// zero agg1 (n*16 float4) and agg2 (n*8 float4) in one kernel
__global__ void k_zero_aggs(int n) {
    int i = blockIdx.x * blockDim.x + threadIdx.x;
    int n16 = n * 16;
    int total = n * 24;
    if (i >= total) return;
    float4 z = make_float4(0.f, 0.f, 0.f, 0.f);
    if (i < n16) reinterpret_cast<float4*>(g_agg1)[i] = z;
    else         reinterpret_cast<float4*>(g_agg2)[i - n16] = z;
}

// degree accumulation over dst
__global__ void k_deg(const int* __restrict__ dst, int E) {
    int e = blockIdx.x * blockDim.x + threadIdx.x;
    if (e < E) atomicAdd(&g_deg[dst[e]], 1.0f);
}

__global__ void k_dis(int n) {
    int i = blockIdx.x * blockDim.x + threadIdx.x;
    if (i < n) g_dis[i] = rsqrtf(g_deg[i]);
}

// ---------------------------------------------------------------------------
// GEMM1: h1s[row, 0:64] = (x[row, 0:128] @ W1) * dis[row]
// Block: 256 threads, 32 rows x 64 cols per block. W1 read via L1 (__ldg),
// x tile staged in smem with +1 padding (conflict-free row-strided reads).
__global__ __launch_bounds__(256) void k_gemm1(const float* __restrict__ x,
                                               const float* __restrict__ W1,
                                               int n) {
    __shared__ float xs[32][129];
    int t = threadIdx.x;
    int rowbase = blockIdx.x * 32;

    // stage x tile: 32 rows x 128 floats = 1024 float4
    for (int i = t; i < 1024; i += 256) {
        int r = i >> 5, c4 = i & 31;
        float4 v = reinterpret_cast<const float4*>(
            x + (size_t)(rowbase + r) * 128)[c4];
        xs[r][c4 * 4 + 0] = v.x;
        xs[r][c4 * 4 + 1] = v.y;
        xs[r][c4 * 4 + 2] = v.z;
        xs[r][c4 * 4 + 3] = v.w;
    }
    __syncthreads();

    int tx = t & 15;          // column group: cols tx*4 .. tx*4+3
    int ty = t >> 4;          // row pair: rows ty*2, ty*2+1
    int r0 = ty * 2, r1 = r0 + 1;

    float4 acc0 = make_float4(0.f, 0.f, 0.f, 0.f);
    float4 acc1 = make_float4(0.f, 0.f, 0.f, 0.f);

    const float4* W1v = reinterpret_cast<const float4*>(W1);  // [128][16] float4
#pragma unroll 4
    for (int k = 0; k < 128; k++) {
        float4 w = __ldg(&W1v[k * 16 + tx]);
        float a0 = xs[r0][k];
        float a1 = xs[r1][k];
        acc0.x += a0 * w.x; acc0.y += a0 * w.y;
        acc0.z += a0 * w.z; acc0.w += a0 * w.w;
        acc1.x += a1 * w.x; acc1.y += a1 * w.y;
        acc1.z += a1 * w.z; acc1.w += a1 * w.w;
    }

    int gr0 = rowbase + r0, gr1 = rowbase + r1;
    if (gr0 < n) {
        float d0 = g_dis[gr0];
        acc0.x *= d0; acc0.y *= d0; acc0.z *= d0; acc0.w *= d0;
        reinterpret_cast<float4*>(g_h1s + (size_t)gr0 * 64)[tx] = acc0;
    }
    if (gr1 < n) {
        float d1 = g_dis[gr1];
        acc1.x *= d1; acc1.y *= d1; acc1.z *= d1; acc1.w *= d1;
        reinterpret_cast<float4*>(g_h1s + (size_t)gr1 * 64)[tx] = acc1;
    }
}

// ---------------------------------------------------------------------------
// Edge scatter: agg[dst, :] += hsrc[src, :]  (CH float4 chunks per edge)
// One thread per (edge, chunk). Vector reduction keeps op count 4x lower.
template <int CH>
__global__ __launch_bounds__(256) void k_scatter(const int* __restrict__ src,
                                                 const int* __restrict__ dst,
                                                 int E) {
    const float* hsrc = (CH == 16) ? g_h1s : g_h2s;
    float* agg = (CH == 16) ? g_agg1 : g_agg2;

    unsigned t = blockIdx.x * blockDim.x + threadIdx.x;
    unsigned total = (unsigned)E * CH;
    if (t >= total) return;
    unsigned e = t / CH;
    unsigned c = t % CH;
    int s = src[e];
    int d = dst[e];
    float4 v = reinterpret_cast<const float4*>(hsrc)[(size_t)s * CH + c];
    float4* p = reinterpret_cast<float4*>(agg) + (size_t)d * CH + c;
    asm volatile("red.global.add.v4.f32 [%0], {%1,%2,%3,%4};"
                 :: "l"(p), "f"(v.x), "f"(v.y), "f"(v.z), "f"(v.w)
                 : "memory");
}

// ---------------------------------------------------------------------------
// Layer-2 fused: h = relu((agg1 + h1s)*dis + b1); h2s = (h @ W2) * dis
// Block: 256 threads, 32 rows.
__global__ __launch_bounds__(256) void k_layer2(const float* __restrict__ b1,
                                                const float* __restrict__ W2,
                                                int n) {
    __shared__ float W2s[64][32];
    __shared__ float hs[32][65];
    __shared__ float b1s[64];

    int t = threadIdx.x;
    // W2: 64x32 = 512 float4 groups of 4
    for (int i = t; i < 512; i += 256)
        reinterpret_cast<float4*>(&W2s[0][0])[i] =
            reinterpret_cast<const float4*>(W2)[i];
    if (t < 64) b1s[t] = b1[t];
    __syncthreads();

    int rowbase = blockIdx.x * 32;
    // compute h for 32 rows x 64 cols
    for (int i = t; i < 2048; i += 256) {
        int r = i >> 6, c = i & 63;
        int gr = rowbase + r;
        size_t idx = (size_t)gr * 64 + c;
        float hv = (g_agg1[idx] + g_h1s[idx]) * g_dis[gr] + b1s[c];
        hs[r][c] = fmaxf(hv, 0.f);
    }
    __syncthreads();

    int tx = t & 31;          // output column
    int rg = t >> 5;          // 0..7 -> rows rg, rg+8, rg+16, rg+24
    float a0 = 0.f, a1 = 0.f, a2 = 0.f, a3 = 0.f;
#pragma unroll 4
    for (int k = 0; k < 64; k++) {
        float w = W2s[k][tx];
        a0 += hs[rg][k] * w;
        a1 += hs[rg + 8][k] * w;
        a2 += hs[rg + 16][k] * w;
        a3 += hs[rg + 24][k] * w;
    }
    int gr;
    gr = rowbase + rg;      g_h2s[(size_t)gr * 32 + tx] = a0 * g_dis[gr];
    gr = rowbase + rg + 8;  g_h2s[(size_t)gr * 32 + tx] = a1 * g_dis[gr];
    gr = rowbase + rg + 16; g_h2s[(size_t)gr * 32 + tx] = a2 * g_dis[gr];
    gr = rowbase + rg + 24; g_h2s[(size_t)gr * 32 + tx] = a3 * g_dis[gr];
}

// ---------------------------------------------------------------------------
// Final: out[i] = relu((agg2+h2s)*dis + b2) @ Wfc + bfc
__global__ __launch_bounds__(256) void k_final(const float* __restrict__ b2,
                                               const float* __restrict__ Wfc,
                                               const float* __restrict__ bfc,
                                               float* __restrict__ out, int n) {
    int i = blockIdx.x * blockDim.x + threadIdx.x;
    if (i >= n) return;
    float di = g_dis[i];
    float acc = bfc[0];
    const float4* a4 = reinterpret_cast<const float4*>(g_agg2 + (size_t)i * 32);
    const float4* h4 = reinterpret_cast<const float4*>(g_h2s + (size_t)i * 32);
    const float4* b4 = reinterpret_cast<const float4*>(b2);
    const float4* w4 = reinterpret_cast<const float4*>(Wfc);
#pragma unroll
    for (int j = 0; j < 8; j++) {
        float4 a = a4[j], h = h4[j], b = b4[j], w = w4[j];
        acc += fmaxf((a.x + h.x) * di + b.x, 0.f) * w.x;
        acc += fmaxf((a.y + h.y) * di + b.y, 0.f) * w.y;
        acc += fmaxf((a.z + h.z) * di + b.z, 0.f) * w.z;
        acc += fmaxf((a.w + h.w) * di + b.w, 0.f) * w.w;
    }
    out[i] = acc;
}

// ---------------------------------------------------------------------------
extern "C" void kernel_launch(void* const* d_in, const int* in_sizes, int n_in,
                              void* d_out, int out_size) {
    const float* x   = (const float*)d_in[0];
    const int*   ei  = (const int*)d_in[1];
    const float* W1  = (const float*)d_in[2];
    const float* b1  = (const float*)d_in[3];
    const float* W2  = (const float*)d_in[4];
    const float* b2  = (const float*)d_in[5];
    const float* Wfc = (const float*)d_in[6];
    const float* bfc = (const float*)d_in[7];
    float* out = (float*)d_out;

    int N = in_sizes[0] / 128;
    int E = in_sizes[1] / 2;
    const int* src = ei;
    const int* dst = ei + E;

    int nb256 = (N + 255) / 256;
    int rb32  = (N + 31) / 32;

    k_init_deg<<<nb256, 256>>>(N);
    k_zero_aggs<<<(N * 24 + 255) / 256, 256>>>(N);
    k_deg<<<(E + 255) / 256, 256>>>(dst, E);
    k_dis<<<nb256, 256>>>(N);

    k_gemm1<<<rb32, 256>>>(x, W1, N);

    {
        long long tot = (long long)E * 16;
        k_scatter<16><<<(unsigned)((tot + 255) / 256), 256>>>(src, dst, E);
    }

    k_layer2<<<rb32, 256>>>(b1, W2, N);

    {
        long long tot = (long long)E * 8;
        k_scatter<8><<<(unsigned)((tot + 255) / 256), 256>>>(src, dst, E);
    }

    k_final<<<nb256, 256>>>(b2, Wfc, bfc, out, N);
}

// round 2
// speedup vs baseline: 1.3744x; 1.3744x over previous
#include <cuda_runtime.h>
#include <cstdint>

#define NMAX 100000
#define EMAX 3200000
#define SCAN_B 512

// Scratch (device globals -- no allocation allowed).
__device__ int   g_cnt[NMAX];        // in-degree (no self loop)
__device__ int   g_cur[NMAX];        // fill cursor
__device__ float g_dis[NMAX];        // rsqrt(deg+1)
__device__ int   g_off[NMAX + 1];    // CSR offsets (by dst)
__device__ int   g_bsum[(NMAX + SCAN_B - 1) / SCAN_B];
__device__ int   g_boff[(NMAX + SCAN_B - 1) / SCAN_B];
__device__ int   g_csr_src[EMAX];    // src ids grouped by dst
__device__ float g_h1s[NMAX * 64];   // (x@W1) * dis[row]
__device__ float g_agg1[NMAX * 64];  // sum over incoming edges of g_h1s[src]
__device__ float g_h2s[NMAX * 32];
__device__ float g_agg2[NMAX * 32];

// ---------------------------------------------------------------------------
__global__ void k_init_cnt(int n) {
    int i = blockIdx.x * blockDim.x + threadIdx.x;
    if (i < n) g_cnt[i] = 0;
}

__global__ void k_count(const int* __restrict__ dst, int E) {
    int e = blockIdx.x * blockDim.x + threadIdx.x;
    if (e < E) atomicAdd(&g_cnt[dst[e]], 1);
}

// dis = rsqrt(cnt+1); zero fill cursor
__global__ void k_dis(int n) {
    int i = blockIdx.x * blockDim.x + threadIdx.x;
    if (i < n) {
        g_dis[i] = rsqrtf((float)(g_cnt[i] + 1));
        g_cur[i] = 0;
    }
}

// ---- 3-kernel exclusive scan of g_cnt into g_off --------------------------
__global__ __launch_bounds__(SCAN_B) void k_scan1(int n) {
    __shared__ int s[SCAN_B];
    int t = threadIdx.x;
    int i = blockIdx.x * SCAN_B + t;
    int v = (i < n) ? g_cnt[i] : 0;
    s[t] = v;
    __syncthreads();
    for (int d = SCAN_B / 2; d > 0; d >>= 1) {
        if (t < d) s[t] += s[t + d];
        __syncthreads();
    }
    if (t == 0) g_bsum[blockIdx.x] = s[0];
}

__global__ void k_scan2(int nb) {
    if (threadIdx.x == 0) {
        int acc = 0;
        for (int b = 0; b < nb; b++) {
            g_boff[b] = acc;
            acc += g_bsum[b];
        }
    }
}

__global__ __launch_bounds__(SCAN_B) void k_scan3(int n) {
    __shared__ int s[SCAN_B];
    int t = threadIdx.x;
    int i = blockIdx.x * SCAN_B + t;
    int v = (i < n) ? g_cnt[i] : 0;
    s[t] = v;
    __syncthreads();
    // Hillis-Steele inclusive scan
    for (int d = 1; d < SCAN_B; d <<= 1) {
        int x = (t >= d) ? s[t - d] : 0;
        __syncthreads();
        s[t] += x;
        __syncthreads();
    }
    int incl = s[t] + g_boff[blockIdx.x];
    if (i < n) {
        g_off[i] = incl - v;           // exclusive
        if (i == n - 1) g_off[n] = incl;
    }
}

__global__ void k_fill(const int* __restrict__ src,
                       const int* __restrict__ dst, int E) {
    int e = blockIdx.x * blockDim.x + threadIdx.x;
    if (e >= E) return;
    int d = dst[e];
    int p = atomicAdd(&g_cur[d], 1);
    g_csr_src[g_off[d] + p] = src[e];
}

// ---------------------------------------------------------------------------
// GEMM1: h1s[row, 0:64] = (x[row, 0:128] @ W1) * dis[row]
__global__ __launch_bounds__(256) void k_gemm1(const float* __restrict__ x,
                                               const float* __restrict__ W1,
                                               int n) {
    __shared__ float xs[32][129];
    int t = threadIdx.x;
    int rowbase = blockIdx.x * 32;

    for (int i = t; i < 1024; i += 256) {
        int r = i >> 5, c4 = i & 31;
        float4 v = reinterpret_cast<const float4*>(
            x + (size_t)(rowbase + r) * 128)[c4];
        xs[r][c4 * 4 + 0] = v.x;
        xs[r][c4 * 4 + 1] = v.y;
        xs[r][c4 * 4 + 2] = v.z;
        xs[r][c4 * 4 + 3] = v.w;
    }
    __syncthreads();

    int tx = t & 15;
    int ty = t >> 4;
    int r0 = ty * 2, r1 = r0 + 1;

    float4 acc0 = make_float4(0.f, 0.f, 0.f, 0.f);
    float4 acc1 = make_float4(0.f, 0.f, 0.f, 0.f);

    const float4* W1v = reinterpret_cast<const float4*>(W1);
#pragma unroll 4
    for (int k = 0; k < 128; k++) {
        float4 w = __ldg(&W1v[k * 16 + tx]);
        float a0 = xs[r0][k];
        float a1 = xs[r1][k];
        acc0.x += a0 * w.x; acc0.y += a0 * w.y;
        acc0.z += a0 * w.z; acc0.w += a0 * w.w;
        acc1.x += a1 * w.x; acc1.y += a1 * w.y;
        acc1.z += a1 * w.z; acc1.w += a1 * w.w;
    }

    int gr0 = rowbase + r0, gr1 = rowbase + r1;
    if (gr0 < n) {
        float d0 = g_dis[gr0];
        acc0.x *= d0; acc0.y *= d0; acc0.z *= d0; acc0.w *= d0;
        reinterpret_cast<float4*>(g_h1s + (size_t)gr0 * 64)[tx] = acc0;
    }
    if (gr1 < n) {
        float d1 = g_dis[gr1];
        acc1.x *= d1; acc1.y *= d1; acc1.z *= d1; acc1.w *= d1;
        reinterpret_cast<float4*>(g_h1s + (size_t)gr1 * 64)[tx] = acc1;
    }
}

// ---------------------------------------------------------------------------
// CSR gather aggregation, layer 1 (64 cols): one warp per dst node.
// Lane l accumulates cols 2l, 2l+1 (float2). src ids shfl-broadcast.
__global__ __launch_bounds__(256) void k_agg1(int n) {
    int warp = (blockIdx.x * blockDim.x + threadIdx.x) >> 5;
    if (warp >= n) return;
    int lane = threadIdx.x & 31;
    int beg = g_off[warp], end = g_off[warp + 1];

    float ax = 0.f, ay = 0.f;
    const float* h = g_h1s;
    for (int e = beg; e < end; e += 32) {
        int m = min(32, end - e);
        int s = (lane < m) ? g_csr_src[e + lane] : 0;
        int j = 0;
        for (; j + 4 <= m; j += 4) {
            int s0 = __shfl_sync(0xffffffffu, s, j);
            int s1 = __shfl_sync(0xffffffffu, s, j + 1);
            int s2 = __shfl_sync(0xffffffffu, s, j + 2);
            int s3 = __shfl_sync(0xffffffffu, s, j + 3);
            float2 v0 = *(const float2*)(h + (size_t)s0 * 64 + lane * 2);
            float2 v1 = *(const float2*)(h + (size_t)s1 * 64 + lane * 2);
            float2 v2 = *(const float2*)(h + (size_t)s2 * 64 + lane * 2);
            float2 v3 = *(const float2*)(h + (size_t)s3 * 64 + lane * 2);
            ax += v0.x + v1.x; ay += v0.y + v1.y;
            ax += v2.x + v3.x; ay += v2.y + v3.y;
        }
        for (; j < m; j++) {
            int sj = __shfl_sync(0xffffffffu, s, j);
            float2 v = *(const float2*)(h + (size_t)sj * 64 + lane * 2);
            ax += v.x; ay += v.y;
        }
    }
    float2 out; out.x = ax; out.y = ay;
    *(float2*)(g_agg1 + (size_t)warp * 64 + lane * 2) = out;
}

// CSR gather aggregation, layer 2 (32 cols): one warp per node, 1 float/lane.
__global__ __launch_bounds__(256) void k_agg2(int n) {
    int warp = (blockIdx.x * blockDim.x + threadIdx.x) >> 5;
    if (warp >= n) return;
    int lane = threadIdx.x & 31;
    int beg = g_off[warp], end = g_off[warp + 1];

    float a = 0.f;
    const float* h = g_h2s;
    for (int e = beg; e < end; e += 32) {
        int m = min(32, end - e);
        int s = (lane < m) ? g_csr_src[e + lane] : 0;
        int j = 0;
        for (; j + 4 <= m; j += 4) {
            int s0 = __shfl_sync(0xffffffffu, s, j);
            int s1 = __shfl_sync(0xffffffffu, s, j + 1);
            int s2 = __shfl_sync(0xffffffffu, s, j + 2);
            int s3 = __shfl_sync(0xffffffffu, s, j + 3);
            float v0 = h[(size_t)s0 * 32 + lane];
            float v1 = h[(size_t)s1 * 32 + lane];
            float v2 = h[(size_t)s2 * 32 + lane];
            float v3 = h[(size_t)s3 * 32 + lane];
            a += v0 + v1 + v2 + v3;
        }
        for (; j < m; j++) {
            int sj = __shfl_sync(0xffffffffu, s, j);
            a += h[(size_t)sj * 32 + lane];
        }
    }
    g_agg2[(size_t)warp * 32 + lane] = a;
}

// ---------------------------------------------------------------------------
// Layer-2 fused: h = relu((agg1 + h1s)*dis + b1); h2s = (h @ W2) * dis
__global__ __launch_bounds__(256) void k_layer2(const float* __restrict__ b1,
                                                const float* __restrict__ W2,
                                                int n) {
    __shared__ float W2s[64][32];
    __shared__ float hs[32][65];
    __shared__ float b1s[64];

    int t = threadIdx.x;
    for (int i = t; i < 512; i += 256)
        reinterpret_cast<float4*>(&W2s[0][0])[i] =
            reinterpret_cast<const float4*>(W2)[i];
    if (t < 64) b1s[t] = b1[t];
    __syncthreads();

    int rowbase = blockIdx.x * 32;
    for (int i = t; i < 2048; i += 256) {
        int r = i >> 6, c = i & 63;
        int gr = rowbase + r;
        size_t idx = (size_t)gr * 64 + c;
        float hv = (g_agg1[idx] + g_h1s[idx]) * g_dis[gr] + b1s[c];
        hs[r][c] = fmaxf(hv, 0.f);
    }
    __syncthreads();

    int tx = t & 31;
    int rg = t >> 5;
    float a0 = 0.f, a1 = 0.f, a2 = 0.f, a3 = 0.f;
#pragma unroll 4
    for (int k = 0; k < 64; k++) {
        float w = W2s[k][tx];
        a0 += hs[rg][k] * w;
        a1 += hs[rg + 8][k] * w;
        a2 += hs[rg + 16][k] * w;
        a3 += hs[rg + 24][k] * w;
    }
    int gr;
    gr = rowbase + rg;      g_h2s[(size_t)gr * 32 + tx] = a0 * g_dis[gr];
    gr = rowbase + rg + 8;  g_h2s[(size_t)gr * 32 + tx] = a1 * g_dis[gr];
    gr = rowbase + rg + 16; g_h2s[(size_t)gr * 32 + tx] = a2 * g_dis[gr];
    gr = rowbase + rg + 24; g_h2s[(size_t)gr * 32 + tx] = a3 * g_dis[gr];
}

// ---------------------------------------------------------------------------
__global__ __launch_bounds__(256) void k_final(const float* __restrict__ b2,
                                               const float* __restrict__ Wfc,
                                               const float* __restrict__ bfc,
                                               float* __restrict__ out, int n) {
    int i = blockIdx.x * blockDim.x + threadIdx.x;
    if (i >= n) return;
    float di = g_dis[i];
    float acc = bfc[0];
    const float4* a4 = reinterpret_cast<const float4*>(g_agg2 + (size_t)i * 32);
    const float4* h4 = reinterpret_cast<const float4*>(g_h2s + (size_t)i * 32);
    const float4* b4 = reinterpret_cast<const float4*>(b2);
    const float4* w4 = reinterpret_cast<const float4*>(Wfc);
#pragma unroll
    for (int j = 0; j < 8; j++) {
        float4 a = a4[j], h = h4[j], b = b4[j], w = w4[j];
        acc += fmaxf((a.x + h.x) * di + b.x, 0.f) * w.x;
        acc += fmaxf((a.y + h.y) * di + b.y, 0.f) * w.y;
        acc += fmaxf((a.z + h.z) * di + b.z, 0.f) * w.z;
        acc += fmaxf((a.w + h.w) * di + b.w, 0.f) * w.w;
    }
    out[i] = acc;
}

// ---------------------------------------------------------------------------
extern "C" void kernel_launch(void* const* d_in, const int* in_sizes, int n_in,
                              void* d_out, int out_size) {
    const float* x   = (const float*)d_in[0];
    const int*   ei  = (const int*)d_in[1];
    const float* W1  = (const float*)d_in[2];
    const float* b1  = (const float*)d_in[3];
    const float* W2  = (const float*)d_in[4];
    const float* b2  = (const float*)d_in[5];
    const float* Wfc = (const float*)d_in[6];
    const float* bfc = (const float*)d_in[7];
    float* out = (float*)d_out;

    int N = in_sizes[0] / 128;
    int E = in_sizes[1] / 2;
    const int* src = ei;
    const int* dst = ei + E;

    int nb256 = (N + 255) / 256;
    int rb32  = (N + 31) / 32;
    int eb256 = (E + 255) / 256;
    int nscan = (N + SCAN_B - 1) / SCAN_B;

    // ---- CSR build ----
    k_init_cnt<<<nb256, 256>>>(N);
    k_count<<<eb256, 256>>>(dst, E);
    k_scan1<<<nscan, SCAN_B>>>(N);
    k_scan2<<<1, 32>>>(nscan);
    k_scan3<<<nscan, SCAN_B>>>(N);
    k_dis<<<nb256, 256>>>(N);
    k_fill<<<eb256, 256>>>(src, dst, E);

    // ---- network ----
    k_gemm1<<<rb32, 256>>>(x, W1, N);
    k_agg1<<<(N * 32 + 255) / 256, 256>>>(N);
    k_layer2<<<rb32, 256>>>(b1, W2, N);
    k_agg2<<<(N * 32 + 255) / 256, 256>>>(N);
    k_final<<<nb256, 256>>>(b2, Wfc, bfc, out, N);
}

// round 3
// speedup vs baseline: 2.1441x; 1.5600x over previous
#include <cuda_runtime.h>
#include <cuda_fp16.h>
#include <cstdint>

#define NMAX 100000
#define EMAX 3200000
#define SCAN_B 512

// Scratch (device globals -- no allocation allowed).
__device__ int     g_cnt[NMAX];        // in-degree (no self loop)
__device__ int     g_cur[NMAX];        // fill cursor
__device__ float   g_dis[NMAX];        // rsqrt(deg+1)
__device__ int     g_off[NMAX + 1];    // CSR offsets (by dst)
__device__ int     g_bsum[(NMAX + SCAN_B - 1) / SCAN_B];
__device__ int     g_boff[(NMAX + SCAN_B - 1) / SCAN_B];
__device__ int     g_csr_src[EMAX];    // src ids grouped by dst
__device__ __half2 g_h1s[NMAX * 32];   // (x@W1)*dis[row], fp16, 64 cols
__device__ __half2 g_h[NMAX * 32];     // relu layer-1 output, fp16, 64 cols
__device__ __half  g_h2s[NMAX * 32];   // (h@W2)*dis[row], fp16, 32 cols

// ---------------------------------------------------------------------------
__global__ void k_init_cnt(int n) {
    int i = blockIdx.x * blockDim.x + threadIdx.x;
    if (i < n) g_cnt[i] = 0;
}

__global__ void k_count(const int* __restrict__ dst, int E) {
    int e = blockIdx.x * blockDim.x + threadIdx.x;
    if (e < E) atomicAdd(&g_cnt[dst[e]], 1);
}

// ---- scan of g_cnt into g_off ---------------------------------------------
__global__ __launch_bounds__(SCAN_B) void k_scan1(int n) {
    __shared__ int s[SCAN_B];
    int t = threadIdx.x;
    int i = blockIdx.x * SCAN_B + t;
    s[t] = (i < n) ? g_cnt[i] : 0;
    __syncthreads();
    for (int d = SCAN_B / 2; d > 0; d >>= 1) {
        if (t < d) s[t] += s[t + d];
        __syncthreads();
    }
    if (t == 0) g_bsum[blockIdx.x] = s[0];
}

// parallel single-block scan over <=256 block sums
__global__ __launch_bounds__(256) void k_scan2(int nb) {
    __shared__ int s[256];
    int t = threadIdx.x;
    int v = (t < nb) ? g_bsum[t] : 0;
    s[t] = v;
    __syncthreads();
    for (int d = 1; d < 256; d <<= 1) {
        int x = (t >= d) ? s[t - d] : 0;
        __syncthreads();
        s[t] += x;
        __syncthreads();
    }
    if (t < nb) g_boff[t] = s[t] - v;  // exclusive
}

// scan3 fused with dis computation + cursor zeroing
__global__ __launch_bounds__(SCAN_B) void k_scan3(int n) {
    __shared__ int s[SCAN_B];
    int t = threadIdx.x;
    int i = blockIdx.x * SCAN_B + t;
    int v = (i < n) ? g_cnt[i] : 0;
    s[t] = v;
    __syncthreads();
    for (int d = 1; d < SCAN_B; d <<= 1) {
        int x = (t >= d) ? s[t - d] : 0;
        __syncthreads();
        s[t] += x;
        __syncthreads();
    }
    int incl = s[t] + g_boff[blockIdx.x];
    if (i < n) {
        g_off[i] = incl - v;
        if (i == n - 1) g_off[n] = incl;
        g_dis[i] = rsqrtf((float)(v + 1));
        g_cur[i] = 0;
    }
}

__global__ void k_fill(const int* __restrict__ src,
                       const int* __restrict__ dst, int E) {
    int e = blockIdx.x * blockDim.x + threadIdx.x;
    if (e >= E) return;
    int d = dst[e];
    int p = atomicAdd(&g_cur[d], 1);
    g_csr_src[g_off[d] + p] = src[e];
}

// ---------------------------------------------------------------------------
// GEMM1: h1s[row, 0:64] = (x[row, 0:128] @ W1) * dis[row]  (fp16 out)
__global__ __launch_bounds__(256) void k_gemm1(const float* __restrict__ x,
                                               const float* __restrict__ W1,
                                               int n) {
    __shared__ float xs[32][129];
    int t = threadIdx.x;
    int rowbase = blockIdx.x * 32;

    for (int i = t; i < 1024; i += 256) {
        int r = i >> 5, c4 = i & 31;
        float4 v = reinterpret_cast<const float4*>(
            x + (size_t)(rowbase + r) * 128)[c4];
        xs[r][c4 * 4 + 0] = v.x;
        xs[r][c4 * 4 + 1] = v.y;
        xs[r][c4 * 4 + 2] = v.z;
        xs[r][c4 * 4 + 3] = v.w;
    }
    __syncthreads();

    int tx = t & 15;          // cols 4tx..4tx+3
    int ty = t >> 4;
    int r0 = ty * 2, r1 = r0 + 1;

    float4 acc0 = make_float4(0.f, 0.f, 0.f, 0.f);
    float4 acc1 = make_float4(0.f, 0.f, 0.f, 0.f);

    const float4* W1v = reinterpret_cast<const float4*>(W1);
#pragma unroll 4
    for (int k = 0; k < 128; k++) {
        float4 w = __ldg(&W1v[k * 16 + tx]);
        float a0 = xs[r0][k];
        float a1 = xs[r1][k];
        acc0.x += a0 * w.x; acc0.y += a0 * w.y;
        acc0.z += a0 * w.z; acc0.w += a0 * w.w;
        acc1.x += a1 * w.x; acc1.y += a1 * w.y;
        acc1.z += a1 * w.z; acc1.w += a1 * w.w;
    }

    int gr0 = rowbase + r0, gr1 = rowbase + r1;
    if (gr0 < n) {
        float d0 = g_dis[gr0];
        g_h1s[(size_t)gr0 * 32 + 2 * tx]     = __floats2half2_rn(acc0.x * d0, acc0.y * d0);
        g_h1s[(size_t)gr0 * 32 + 2 * tx + 1] = __floats2half2_rn(acc0.z * d0, acc0.w * d0);
    }
    if (gr1 < n) {
        float d1 = g_dis[gr1];
        g_h1s[(size_t)gr1 * 32 + 2 * tx]     = __floats2half2_rn(acc1.x * d1, acc1.y * d1);
        g_h1s[(size_t)gr1 * 32 + 2 * tx + 1] = __floats2half2_rn(acc1.z * d1, acc1.w * d1);
    }
}

// ---------------------------------------------------------------------------
// agg1 + layer-1 activation fused: one warp per dst node, lane holds cols
// 2l,2l+1. h[node] = relu((sum_src h1s[src] + h1s[node]) * dis + b1)  (fp16)
__global__ __launch_bounds__(256) void k_agg1(const float* __restrict__ b1, int n) {
    int warp = (blockIdx.x * blockDim.x + threadIdx.x) >> 5;
    if (warp >= n) return;
    int lane = threadIdx.x & 31;
    int beg = g_off[warp], end = g_off[warp + 1];

    float ax = 0.f, ay = 0.f;
    const __half2* h = g_h1s;
    for (int e = beg; e < end; e += 32) {
        int m = min(32, end - e);
        int s = (lane < m) ? g_csr_src[e + lane] : 0;
        int j = 0;
        for (; j + 8 <= m; j += 8) {
            int s0 = __shfl_sync(0xffffffffu, s, j);
            int s1 = __shfl_sync(0xffffffffu, s, j + 1);
            int s2 = __shfl_sync(0xffffffffu, s, j + 2);
            int s3 = __shfl_sync(0xffffffffu, s, j + 3);
            int s4 = __shfl_sync(0xffffffffu, s, j + 4);
            int s5 = __shfl_sync(0xffffffffu, s, j + 5);
            int s6 = __shfl_sync(0xffffffffu, s, j + 6);
            int s7 = __shfl_sync(0xffffffffu, s, j + 7);
            float2 v0 = __half22float2(h[(size_t)s0 * 32 + lane]);
            float2 v1 = __half22float2(h[(size_t)s1 * 32 + lane]);
            float2 v2 = __half22float2(h[(size_t)s2 * 32 + lane]);
            float2 v3 = __half22float2(h[(size_t)s3 * 32 + lane]);
            float2 v4 = __half22float2(h[(size_t)s4 * 32 + lane]);
            float2 v5 = __half22float2(h[(size_t)s5 * 32 + lane]);
            float2 v6 = __half22float2(h[(size_t)s6 * 32 + lane]);
            float2 v7 = __half22float2(h[(size_t)s7 * 32 + lane]);
            ax += (v0.x + v1.x) + (v2.x + v3.x) + (v4.x + v5.x) + (v6.x + v7.x);
            ay += (v0.y + v1.y) + (v2.y + v3.y) + (v4.y + v5.y) + (v6.y + v7.y);
        }
        for (; j < m; j++) {
            int sj = __shfl_sync(0xffffffffu, s, j);
            float2 v = __half22float2(h[(size_t)sj * 32 + lane]);
            ax += v.x; ay += v.y;
        }
    }
    float di = g_dis[warp];
    float2 self = __half22float2(h[(size_t)warp * 32 + lane]);
    float2 bb = reinterpret_cast<const float2*>(b1)[lane];
    float hx = fmaxf((ax + self.x) * di + bb.x, 0.f);
    float hy = fmaxf((ay + self.y) * di + bb.y, 0.f);
    g_h[(size_t)warp * 32 + lane] = __floats2half2_rn(hx, hy);
}

// ---------------------------------------------------------------------------
// layer2 GEMM: h2s = (h @ W2) * dis   (h fp16 in, h2s fp16 out)
__global__ __launch_bounds__(256) void k_layer2(const float* __restrict__ W2,
                                                int n) {
    __shared__ float W2s[64][32];
    __shared__ float hs[32][65];

    int t = threadIdx.x;
    for (int i = t; i < 512; i += 256)
        reinterpret_cast<float4*>(&W2s[0][0])[i] =
            reinterpret_cast<const float4*>(W2)[i];

    int rowbase = blockIdx.x * 32;
    // stage h tile: 32 rows x 32 half2
    for (int i = t; i < 1024; i += 256) {
        int r = i >> 5, c = i & 31;
        float2 v = __half22float2(g_h[(size_t)(rowbase + r) * 32 + c]);
        hs[r][c * 2] = v.x;
        hs[r][c * 2 + 1] = v.y;
    }
    __syncthreads();

    int tx = t & 31;
    int rg = t >> 5;
    float a0 = 0.f, a1 = 0.f, a2 = 0.f, a3 = 0.f;
#pragma unroll 4
    for (int k = 0; k < 64; k++) {
        float w = W2s[k][tx];
        a0 += hs[rg][k] * w;
        a1 += hs[rg + 8][k] * w;
        a2 += hs[rg + 16][k] * w;
        a3 += hs[rg + 24][k] * w;
    }
    int gr;
    gr = rowbase + rg;      g_h2s[(size_t)gr * 32 + tx] = __float2half_rn(a0 * g_dis[gr]);
    gr = rowbase + rg + 8;  g_h2s[(size_t)gr * 32 + tx] = __float2half_rn(a1 * g_dis[gr]);
    gr = rowbase + rg + 16; g_h2s[(size_t)gr * 32 + tx] = __float2half_rn(a2 * g_dis[gr]);
    gr = rowbase + rg + 24; g_h2s[(size_t)gr * 32 + tx] = __float2half_rn(a3 * g_dis[gr]);
}

// ---------------------------------------------------------------------------
// agg2 + final FC fused: one warp per node, lane holds one of 32 cols.
// out[i] = relu((agg + self)*dis + b2) . Wfc + bfc
__global__ __launch_bounds__(256) void k_agg2_final(const float* __restrict__ b2,
                                                    const float* __restrict__ Wfc,
                                                    const float* __restrict__ bfc,
                                                    float* __restrict__ out, int n) {
    int warp = (blockIdx.x * blockDim.x + threadIdx.x) >> 5;
    if (warp >= n) return;
    int lane = threadIdx.x & 31;
    int beg = g_off[warp], end = g_off[warp + 1];

    float a = 0.f;
    const __half* h = g_h2s;
    for (int e = beg; e < end; e += 32) {
        int m = min(32, end - e);
        int s = (lane < m) ? g_csr_src[e + lane] : 0;
        int j = 0;
        for (; j + 8 <= m; j += 8) {
            int s0 = __shfl_sync(0xffffffffu, s, j);
            int s1 = __shfl_sync(0xffffffffu, s, j + 1);
            int s2 = __shfl_sync(0xffffffffu, s, j + 2);
            int s3 = __shfl_sync(0xffffffffu, s, j + 3);
            int s4 = __shfl_sync(0xffffffffu, s, j + 4);
            int s5 = __shfl_sync(0xffffffffu, s, j + 5);
            int s6 = __shfl_sync(0xffffffffu, s, j + 6);
            int s7 = __shfl_sync(0xffffffffu, s, j + 7);
            float v0 = __half2float(h[(size_t)s0 * 32 + lane]);
            float v1 = __half2float(h[(size_t)s1 * 32 + lane]);
            float v2 = __half2float(h[(size_t)s2 * 32 + lane]);
            float v3 = __half2float(h[(size_t)s3 * 32 + lane]);
            float v4 = __half2float(h[(size_t)s4 * 32 + lane]);
            float v5 = __half2float(h[(size_t)s5 * 32 + lane]);
            float v6 = __half2float(h[(size_t)s6 * 32 + lane]);
            float v7 = __half2float(h[(size_t)s7 * 32 + lane]);
            a += (v0 + v1) + (v2 + v3) + (v4 + v5) + (v6 + v7);
        }
        for (; j < m; j++) {
            int sj = __shfl_sync(0xffffffffu, s, j);
            a += __half2float(h[(size_t)sj * 32 + lane]);
        }
    }
    float di = g_dis[warp];
    float self = __half2float(h[(size_t)warp * 32 + lane]);
    float o = fmaxf((a + self) * di + b2[lane], 0.f) * Wfc[lane];
#pragma unroll
    for (int d = 16; d > 0; d >>= 1)
        o += __shfl_xor_sync(0xffffffffu, o, d);
    if (lane == 0) out[warp] = o + bfc[0];
}

// ---------------------------------------------------------------------------
extern "C" void kernel_launch(void* const* d_in, const int* in_sizes, int n_in,
                              void* d_out, int out_size) {
    const float* x   = (const float*)d_in[0];
    const int*   ei  = (const int*)d_in[1];
    const float* W1  = (const float*)d_in[2];
    const float* b1  = (const float*)d_in[3];
    const float* W2  = (const float*)d_in[4];
    const float* b2  = (const float*)d_in[5];
    const float* Wfc = (const float*)d_in[6];
    const float* bfc = (const float*)d_in[7];
    float* out = (float*)d_out;

    int N = in_sizes[0] / 128;
    int E = in_sizes[1] / 2;
    const int* src = ei;
    const int* dst = ei + E;

    int nb256 = (N + 255) / 256;
    int rb32  = (N + 31) / 32;
    int eb256 = (E + 255) / 256;
    int nscan = (N + SCAN_B - 1) / SCAN_B;

    // ---- CSR build ----
    k_init_cnt<<<nb256, 256>>>(N);
    k_count<<<eb256, 256>>>(dst, E);
    k_scan1<<<nscan, SCAN_B>>>(N);
    k_scan2<<<1, 256>>>(nscan);
    k_scan3<<<nscan, SCAN_B>>>(N);
    k_fill<<<eb256, 256>>>(src, dst, E);

    // ---- network ----
    k_gemm1<<<rb32, 256>>>(x, W1, N);
    k_agg1<<<(N * 32 + 255) / 256, 256>>>(b1, N);
    k_layer2<<<rb32, 256>>>(W2, N);
    k_agg2_final<<<(N * 32 + 255) / 256, 256>>>(b2, Wfc, bfc, out, N);
}

// round 4
// speedup vs baseline: 2.2238x; 1.0372x over previous
#include <cuda_runtime.h>
#include <cuda_fp16.h>
#include <mma.h>
#include <cstdint>

using namespace nvcuda;

#define NMAX 100000
#define EMAX 3200000
#define SCAN_B 512

// Scratch (device globals -- no allocation allowed).
__device__ int     g_cnt[NMAX];        // in-degree (no self loop)
__device__ int     g_cur[NMAX];        // fill cursor
__device__ float   g_dis[NMAX];        // rsqrt(deg+1)
__device__ int     g_off[NMAX + 1];    // CSR offsets (by dst)
__device__ int     g_bsum[(NMAX + SCAN_B - 1) / SCAN_B];
__device__ int     g_boff[(NMAX + SCAN_B - 1) / SCAN_B];
__device__ int     g_csr_src[EMAX];    // src ids grouped by dst
__device__ __half2 g_h1s[NMAX * 32];   // (x@W1)*dis[row], fp16, 64 cols
__device__ __half  g_h2s[NMAX * 32];   // (h@W2)*dis[row], fp16, 32 cols

// ---------------------------------------------------------------------------
__global__ void k_init_cnt(int n) {
    int i = blockIdx.x * blockDim.x + threadIdx.x;
    if (i < n) g_cnt[i] = 0;
}

__global__ void k_count(const int* __restrict__ dst, int E) {
    int e = blockIdx.x * blockDim.x + threadIdx.x;
    if (e < E) atomicAdd(&g_cnt[dst[e]], 1);
}

// ---- scan of g_cnt into g_off ---------------------------------------------
__global__ __launch_bounds__(SCAN_B) void k_scan1(int n) {
    __shared__ int s[SCAN_B];
    int t = threadIdx.x;
    int i = blockIdx.x * SCAN_B + t;
    s[t] = (i < n) ? g_cnt[i] : 0;
    __syncthreads();
    for (int d = SCAN_B / 2; d > 0; d >>= 1) {
        if (t < d) s[t] += s[t + d];
        __syncthreads();
    }
    if (t == 0) g_bsum[blockIdx.x] = s[0];
}

__global__ __launch_bounds__(256) void k_scan2(int nb) {
    __shared__ int s[256];
    int t = threadIdx.x;
    int v = (t < nb) ? g_bsum[t] : 0;
    s[t] = v;
    __syncthreads();
    for (int d = 1; d < 256; d <<= 1) {
        int x = (t >= d) ? s[t - d] : 0;
        __syncthreads();
        s[t] += x;
        __syncthreads();
    }
    if (t < nb) g_boff[t] = s[t] - v;  // exclusive
}

__global__ __launch_bounds__(SCAN_B) void k_scan3(int n) {
    __shared__ int s[SCAN_B];
    int t = threadIdx.x;
    int i = blockIdx.x * SCAN_B + t;
    int v = (i < n) ? g_cnt[i] : 0;
    s[t] = v;
    __syncthreads();
    for (int d = 1; d < SCAN_B; d <<= 1) {
        int x = (t >= d) ? s[t - d] : 0;
        __syncthreads();
        s[t] += x;
        __syncthreads();
    }
    int incl = s[t] + g_boff[blockIdx.x];
    if (i < n) {
        g_off[i] = incl - v;
        if (i == n - 1) g_off[n] = incl;
        g_dis[i] = rsqrtf((float)(v + 1));
        g_cur[i] = 0;
    }
}

// ---------------------------------------------------------------------------
// Fused: CSR fill (edge slice per block, overlaps as memory work) +
// GEMM1 via wmma: h1s[32 rows x 64 cols] = (x[32x128] @ W1[128x64]) * dis
// Block: 256 threads (8 warps). Each warp one 16x16 output tile.
// smem phase1: A fp16 32x136, B fp16 128x72. phase2: C fp32 32x64 (reuses A).
#define XS_LD 136
#define W1_LD 72
__global__ __launch_bounds__(256) void k_gemm1_fill(
        const float* __restrict__ x, const float* __restrict__ W1,
        const int* __restrict__ src, const int* __restrict__ dst,
        int n, int E, int chunk) {
    __shared__ __align__(16) __half xs[32 * XS_LD];     // 8704 B
    __shared__ __align__(16) __half w1s[128 * W1_LD];   // 18432 B

    int t = threadIdx.x;
    int rowbase = blockIdx.x * 32;

    // ---- CSR fill slice (independent memory work; issue first) ----
    {
        int e0 = blockIdx.x * chunk;
        int e1 = min(E, e0 + chunk);
        for (int e = e0 + t; e < e1; e += 256) {
            int d = dst[e];
            int p = atomicAdd(&g_cur[d], 1);
            g_csr_src[g_off[d] + p] = src[e];
        }
    }

    // ---- stage A (x tile) as fp16 ----
    for (int i = t; i < 1024; i += 256) {
        int r = i >> 5, c4 = i & 31;
        float4 v = reinterpret_cast<const float4*>(
            x + (size_t)(rowbase + r) * 128)[c4];
        __half2* p = reinterpret_cast<__half2*>(&xs[r * XS_LD + c4 * 4]);
        p[0] = __floats2half2_rn(v.x, v.y);
        p[1] = __floats2half2_rn(v.z, v.w);
    }
    // ---- stage B (W1) as fp16 ----
    for (int i = t; i < 2048; i += 256) {
        int k = i >> 4, c4 = i & 15;
        float4 v = reinterpret_cast<const float4*>(W1)[k * 16 + c4];
        __half2* p = reinterpret_cast<__half2*>(&w1s[k * W1_LD + c4 * 4]);
        p[0] = __floats2half2_rn(v.x, v.y);
        p[1] = __floats2half2_rn(v.z, v.w);
    }
    __syncthreads();

    // ---- wmma: warp w -> rows 16*(w&1), cols 16*(w>>1) ----
    int w = t >> 5;
    int mrow = (w & 1) * 16;
    int ncol = (w >> 1) * 16;

    wmma::fragment<wmma::accumulator, 16, 16, 16, float> acc;
    wmma::fill_fragment(acc, 0.0f);
#pragma unroll
    for (int k0 = 0; k0 < 8; k0++) {
        wmma::fragment<wmma::matrix_a, 16, 16, 16, __half, wmma::row_major> fa;
        wmma::fragment<wmma::matrix_b, 16, 16, 16, __half, wmma::row_major> fb;
        wmma::load_matrix_sync(fa, &xs[mrow * XS_LD + k0 * 16], XS_LD);
        wmma::load_matrix_sync(fb, &w1s[(k0 * 16) * W1_LD + ncol], W1_LD);
        wmma::mma_sync(acc, fa, fb, acc);
    }
    __syncthreads();  // all A-reads done before C overwrites xs region

    float* cs = reinterpret_cast<float*>(xs);  // 32 x 64 fp32 = 8192 B
    wmma::store_matrix_sync(&cs[mrow * 64 + ncol], acc, 64, wmma::mem_row_major);
    __syncthreads();

    // ---- epilogue: scale by dis, convert fp16, store ----
    for (int i = t; i < 512; i += 256) {
        int r = i >> 4, c4 = i & 15;
        int gr = rowbase + r;
        float d = g_dis[gr];
        float4 v = reinterpret_cast<const float4*>(cs)[i];
        g_h1s[(size_t)gr * 32 + 2 * c4]     = __floats2half2_rn(v.x * d, v.y * d);
        g_h1s[(size_t)gr * 32 + 2 * c4 + 1] = __floats2half2_rn(v.z * d, v.w * d);
    }
}

// ---------------------------------------------------------------------------
// Fused agg1 + layer-1 activation + layer-2 GEMM:
// one warp per dst node; lane l accumulates cols 2l,2l+1 of the gather;
// h = relu((agg + self)*dis + b1) stays in registers (fp32);
// then h2s[node, lane] = (sum_k h[k]*W2[k][lane]) * dis via shfl mini-GEMM.
__global__ __launch_bounds__(256) void k_agg1_l2(const float* __restrict__ b1,
                                                 const float* __restrict__ W2,
                                                 int n) {
    __shared__ float W2s[64 * 32];
    int t = threadIdx.x;
    for (int i = t; i < 512; i += 256)
        reinterpret_cast<float4*>(W2s)[i] = reinterpret_cast<const float4*>(W2)[i];
    __syncthreads();

    int warp = (blockIdx.x * blockDim.x + t) >> 5;
    if (warp >= n) return;
    int lane = t & 31;
    int beg = g_off[warp], end = g_off[warp + 1];

    float ax = 0.f, ay = 0.f;
    const __half2* h = g_h1s;
    for (int e = beg; e < end; e += 32) {
        int m = min(32, end - e);
        int s = (lane < m) ? g_csr_src[e + lane] : 0;
        int j = 0;
        for (; j + 8 <= m; j += 8) {
            int s0 = __shfl_sync(0xffffffffu, s, j);
            int s1 = __shfl_sync(0xffffffffu, s, j + 1);
            int s2 = __shfl_sync(0xffffffffu, s, j + 2);
            int s3 = __shfl_sync(0xffffffffu, s, j + 3);
            int s4 = __shfl_sync(0xffffffffu, s, j + 4);
            int s5 = __shfl_sync(0xffffffffu, s, j + 5);
            int s6 = __shfl_sync(0xffffffffu, s, j + 6);
            int s7 = __shfl_sync(0xffffffffu, s, j + 7);
            float2 v0 = __half22float2(h[(size_t)s0 * 32 + lane]);
            float2 v1 = __half22float2(h[(size_t)s1 * 32 + lane]);
            float2 v2 = __half22float2(h[(size_t)s2 * 32 + lane]);
            float2 v3 = __half22float2(h[(size_t)s3 * 32 + lane]);
            float2 v4 = __half22float2(h[(size_t)s4 * 32 + lane]);
            float2 v5 = __half22float2(h[(size_t)s5 * 32 + lane]);
            float2 v6 = __half22float2(h[(size_t)s6 * 32 + lane]);
            float2 v7 = __half22float2(h[(size_t)s7 * 32 + lane]);
            ax += (v0.x + v1.x) + (v2.x + v3.x) + (v4.x + v5.x) + (v6.x + v7.x);
            ay += (v0.y + v1.y) + (v2.y + v3.y) + (v4.y + v5.y) + (v6.y + v7.y);
        }
        for (; j < m; j++) {
            int sj = __shfl_sync(0xffffffffu, s, j);
            float2 v = __half22float2(h[(size_t)sj * 32 + lane]);
            ax += v.x; ay += v.y;
        }
    }
    float di = g_dis[warp];
    float2 self = __half22float2(h[(size_t)warp * 32 + lane]);
    float2 bb = reinterpret_cast<const float2*>(b1)[lane];
    float hx = fmaxf((ax + self.x) * di + bb.x, 0.f);
    float hy = fmaxf((ay + self.y) * di + bb.y, 0.f);

    // mini-GEMM: out col = lane; broadcast h over lanes
    float acc = 0.f;
#pragma unroll
    for (int j = 0; j < 32; j++) {
        float hxj = __shfl_sync(0xffffffffu, hx, j);
        float hyj = __shfl_sync(0xffffffffu, hy, j);
        acc += hxj * W2s[(2 * j) * 32 + lane];
        acc += hyj * W2s[(2 * j + 1) * 32 + lane];
    }
    g_h2s[(size_t)warp * 32 + lane] = __float2half_rn(acc * di);
}

// ---------------------------------------------------------------------------
// agg2 + final FC fused: one warp per node, lane holds one of 32 cols.
__global__ __launch_bounds__(256) void k_agg2_final(const float* __restrict__ b2,
                                                    const float* __restrict__ Wfc,
                                                    const float* __restrict__ bfc,
                                                    float* __restrict__ out, int n) {
    int warp = (blockIdx.x * blockDim.x + threadIdx.x) >> 5;
    if (warp >= n) return;
    int lane = threadIdx.x & 31;
    int beg = g_off[warp], end = g_off[warp + 1];

    float a = 0.f;
    const __half* h = g_h2s;
    for (int e = beg; e < end; e += 32) {
        int m = min(32, end - e);
        int s = (lane < m) ? g_csr_src[e + lane] : 0;
        int j = 0;
        for (; j + 8 <= m; j += 8) {
            int s0 = __shfl_sync(0xffffffffu, s, j);
            int s1 = __shfl_sync(0xffffffffu, s, j + 1);
            int s2 = __shfl_sync(0xffffffffu, s, j + 2);
            int s3 = __shfl_sync(0xffffffffu, s, j + 3);
            int s4 = __shfl_sync(0xffffffffu, s, j + 4);
            int s5 = __shfl_sync(0xffffffffu, s, j + 5);
            int s6 = __shfl_sync(0xffffffffu, s, j + 6);
            int s7 = __shfl_sync(0xffffffffu, s, j + 7);
            float v0 = __half2float(h[(size_t)s0 * 32 + lane]);
            float v1 = __half2float(h[(size_t)s1 * 32 + lane]);
            float v2 = __half2float(h[(size_t)s2 * 32 + lane]);
            float v3 = __half2float(h[(size_t)s3 * 32 + lane]);
            float v4 = __half2float(h[(size_t)s4 * 32 + lane]);
            float v5 = __half2float(h[(size_t)s5 * 32 + lane]);
            float v6 = __half2float(h[(size_t)s6 * 32 + lane]);
            float v7 = __half2float(h[(size_t)s7 * 32 + lane]);
            a += (v0 + v1) + (v2 + v3) + (v4 + v5) + (v6 + v7);
        }
        for (; j < m; j++) {
            int sj = __shfl_sync(0xffffffffu, s, j);
            a += __half2float(h[(size_t)sj * 32 + lane]);
        }
    }
    float di = g_dis[warp];
    float self = __half2float(h[(size_t)warp * 32 + lane]);
    float o = fmaxf((a + self) * di + b2[lane], 0.f) * Wfc[lane];
#pragma unroll
    for (int d = 16; d > 0; d >>= 1)
        o += __shfl_xor_sync(0xffffffffu, o, d);
    if (lane == 0) out[warp] = o + bfc[0];
}

// ---------------------------------------------------------------------------
extern "C" void kernel_launch(void* const* d_in, const int* in_sizes, int n_in,
                              void* d_out, int out_size) {
    const float* x   = (const float*)d_in[0];
    const int*   ei  = (const int*)d_in[1];
    const float* W1  = (const float*)d_in[2];
    const float* b1  = (const float*)d_in[3];
    const float* W2  = (const float*)d_in[4];
    const float* b2  = (const float*)d_in[5];
    const float* Wfc = (const float*)d_in[6];
    const float* bfc = (const float*)d_in[7];
    float* out = (float*)d_out;

    int N = in_sizes[0] / 128;
    int E = in_sizes[1] / 2;
    const int* src = ei;
    const int* dst = ei + E;

    int nb256 = (N + 255) / 256;
    int rb32  = (N + 31) / 32;      // gemm blocks (N divisible by 32 here)
    int eb256 = (E + 255) / 256;
    int nscan = (N + SCAN_B - 1) / SCAN_B;
    int chunk = (E + rb32 - 1) / rb32;

    // ---- CSR build prefix ----
    k_init_cnt<<<nb256, 256>>>(N);
    k_count<<<eb256, 256>>>(dst, E);
    k_scan1<<<nscan, SCAN_B>>>(N);
    k_scan2<<<1, 256>>>(nscan);
    k_scan3<<<nscan, SCAN_B>>>(N);

    // ---- fused fill + GEMM1 ----
    k_gemm1_fill<<<rb32, 256>>>(x, W1, src, dst, N, E, chunk);

    // ---- fused agg1 + relu + layer2 GEMM ----
    k_agg1_l2<<<(N * 32 + 255) / 256, 256>>>(b1, W2, N);

    // ---- fused agg2 + final FC ----
    k_agg2_final<<<(N * 32 + 255) / 256, 256>>>(b2, Wfc, bfc, out, N);
}